// round 1
// baseline (speedup 1.0000x reference)
#include <cuda_runtime.h>
#include <cstdint>
#include <math.h>

#define BB 4
#define SS 2048
#define DD 2048
#define HH 16
#define MM (BB*SS)   /* 8192 */

// ---------------- scratch (allocation-free: __device__ globals) ----------------
__device__ float g_S1[(size_t)MM*DD];   // V -> pooled -> H2(+x)
__device__ float g_S2[(size_t)MM*DD];   // op
__device__ float g_S3[(size_t)MM*DD];   // hidden after ff1
__device__ float g_logits[MM*HH];
__device__ float g_coef[MM*HH];
__device__ float g_gmax[BB*HH];
__device__ float g_csum[BB*8*DD];

// ---------------- helpers ----------------
__device__ __forceinline__ uint32_t f2tf(float f){
    uint32_t u; asm("cvt.rna.tf32.f32 %0, %1;" : "=r"(u) : "f"(f)); return u;
}

__device__ __forceinline__ void mma8(float (&c)[4], const uint32_t (&a)[4], const uint32_t (&b)[2]){
    asm volatile("mma.sync.aligned.m16n8k8.row.col.f32.tf32.tf32.f32 "
        "{%0,%1,%2,%3}, {%4,%5,%6,%7}, {%8,%9}, {%0,%1,%2,%3};\n"
        : "+f"(c[0]), "+f"(c[1]), "+f"(c[2]), "+f"(c[3])
        : "r"(a[0]), "r"(a[1]), "r"(a[2]), "r"(a[3]), "r"(b[0]), "r"(b[1]));
}

// ---------------- TF32 tiled GEMM ----------------
// C[M, 2048] = A[M, Ktot] * Bw[Ktot, 2048]   (all row-major, row stride 2048)
// SPLITK: A covers k in [0,2048), A2 covers k in [2048,4096)  (logical concat)
// Epilogue: +bias[col], +vec[(row>>11)*2048+col], relu, +resid[row*2048+col]
template<bool SPLITK,bool ADDBIAS,bool ADDVEC,bool RELU,bool ADDRESID>
__global__ __launch_bounds__(256,2)
void k_gemm(const float* __restrict__ A, const float* __restrict__ A2,
            const float* __restrict__ Bw, float* __restrict__ C,
            const float* __restrict__ bias, const float* __restrict__ vec,
            const float* __restrict__ resid, int Ktot)
{
    __shared__ __align__(16) uint32_t As[128*32];  // [m][k], XOR-swizzled in float4 groups
    __shared__ __align__(16) uint32_t Bs[32*128];  // [k][n], XOR-swizzled in float4 groups

    const int tid  = threadIdx.x;
    const int bM   = blockIdx.y << 7;
    const int bN   = blockIdx.x << 7;
    const int lane = tid & 31, warp = tid >> 5;
    const int wm   = (warp & 3) << 5;   // warp M offset (4 warps along M)
    const int wn   = (warp >> 2) << 6;  // warp N offset (2 warps along N)
    const int gid  = lane >> 2, tig = lane & 3;

    float acc[2][8][4];
    #pragma unroll
    for(int i=0;i<2;i++)
        #pragma unroll
        for(int j=0;j<8;j++)
            #pragma unroll
            for(int k=0;k<4;k++) acc[i][j][k]=0.f;

    const int ntiles = Ktot >> 5;
    for(int kt=0; kt<ntiles; kt++){
        const int kbase = kt << 5;
        const float* srcA = A; int koff = kbase;
        if (SPLITK && kbase >= DD){ srcA = A2; koff = kbase - DD; }

        // global -> regs (max MLP), then cvt.rna -> swizzled smem
        float4 va[4], vb[4];
        #pragma unroll
        for(int i=0;i<4;i++){
            int f = tid + (i<<8);
            int r = f>>3, c4 = f&7;           // A: 128 rows x 8 float4
            va[i] = *(const float4*)(srcA + (size_t)(bM+r)*DD + koff + (c4<<2));
            int rb = f>>5, c4b = f&31;        // B: 32 rows x 32 float4
            vb[i] = *(const float4*)(Bw + (size_t)(kbase+rb)*DD + bN + (c4b<<2));
        }
        #pragma unroll
        for(int i=0;i<4;i++){
            int f = tid + (i<<8);
            int r = f>>3, c4 = f&7;
            *(uint4*)&As[(r*8 + (c4 ^ (r&7)))<<2] =
                make_uint4(f2tf(va[i].x),f2tf(va[i].y),f2tf(va[i].z),f2tf(va[i].w));
            int rb = f>>5, c4b = f&31;
            *(uint4*)&Bs[(rb*32 + (c4b ^ ((rb&3)<<1)))<<2] =
                make_uint4(f2tf(vb[i].x),f2tf(vb[i].y),f2tf(vb[i].z),f2tf(vb[i].w));
        }
        __syncthreads();

        #pragma unroll
        for(int kk=0; kk<32; kk+=8){
            uint32_t afr[2][4];
            const int c0 = kk>>2, c1 = (kk>>2)+1;
            #pragma unroll
            for(int mt=0;mt<2;mt++){
                int r0 = wm + (mt<<4) + gid;
                int r1 = r0 + 8;
                afr[mt][0] = As[ (r0<<5) + ((c0 ^ (r0&7))<<2) + tig ];
                afr[mt][1] = As[ (r1<<5) + ((c0 ^ (r1&7))<<2) + tig ];
                afr[mt][2] = As[ (r0<<5) + ((c1 ^ (r0&7))<<2) + tig ];
                afr[mt][3] = As[ (r1<<5) + ((c1 ^ (r1&7))<<2) + tig ];
            }
            uint32_t bfr[8][2];
            const int rB0 = kk + tig, rB1 = kk + tig + 4;
            const int sw  = (tig<<1);   // row&3 == tig for both rB0, rB1
            #pragma unroll
            for(int nt=0;nt<8;nt++){
                int cc = wn + (nt<<3) + gid;
                int cg = cc>>2, ce = cc&3;
                bfr[nt][0] = Bs[ (rB0<<7) + ((cg ^ sw)<<2) + ce ];
                bfr[nt][1] = Bs[ (rB1<<7) + ((cg ^ sw)<<2) + ce ];
            }
            #pragma unroll
            for(int mt=0;mt<2;mt++)
                #pragma unroll
                for(int nt=0;nt<8;nt++)
                    mma8(acc[mt][nt], afr[mt], bfr[nt]);
        }
        __syncthreads();
    }

    // epilogue
    #pragma unroll
    for(int mt=0;mt<2;mt++){
        #pragma unroll
        for(int nt=0;nt<8;nt++){
            int col = bN + wn + (nt<<3) + (tig<<1);
            #pragma unroll
            for(int rr=0;rr<2;rr++){
                int row = bM + wm + (mt<<4) + gid + (rr<<3);
                float v0 = acc[mt][nt][rr*2+0];
                float v1 = acc[mt][nt][rr*2+1];
                if (ADDBIAS){ v0 += bias[col]; v1 += bias[col+1]; }
                if (ADDVEC){ int b0 = row>>11; v0 += vec[b0*DD+col]; v1 += vec[b0*DD+col+1]; }
                if (RELU){ v0 = fmaxf(v0,0.f); v1 = fmaxf(v1,0.f); }
                if (ADDRESID){
                    v0 += resid[(size_t)row*DD+col];
                    v1 += resid[(size_t)row*DD+col+1];
                }
                *(float2*)(C + (size_t)row*DD + col) = make_float2(v0,v1);
            }
        }
    }
}

// ---------------- attention gate: logits = x @ W_att (fp32 exact) ----------------
__global__ void k_logits(const float* __restrict__ x, const float* __restrict__ Watt,
                         float* __restrict__ logits)
{
    const int row = blockIdx.x;
    const float* xr = x + (size_t)row*DD;
    float acc[HH];
    #pragma unroll
    for(int h=0;h<HH;h++) acc[h]=0.f;
    for(int d=threadIdx.x; d<DD; d+=256){
        float xv = xr[d];
        const float4* w4 = (const float4*)(Watt + (size_t)d*HH);
        float4 w0=w4[0], w1=w4[1], w2=w4[2], w3=w4[3];
        acc[0]+=xv*w0.x; acc[1]+=xv*w0.y; acc[2]+=xv*w0.z; acc[3]+=xv*w0.w;
        acc[4]+=xv*w1.x; acc[5]+=xv*w1.y; acc[6]+=xv*w1.z; acc[7]+=xv*w1.w;
        acc[8]+=xv*w2.x; acc[9]+=xv*w2.y; acc[10]+=xv*w2.z; acc[11]+=xv*w2.w;
        acc[12]+=xv*w3.x; acc[13]+=xv*w3.y; acc[14]+=xv*w3.z; acc[15]+=xv*w3.w;
    }
    #pragma unroll
    for(int h=0;h<HH;h++){
        #pragma unroll
        for(int o=16;o>0;o>>=1) acc[h] += __shfl_xor_sync(0xffffffffu, acc[h], o);
    }
    __shared__ float red[8][HH];
    int warp = threadIdx.x>>5, lanei = threadIdx.x&31;
    if(lanei==0){
        #pragma unroll
        for(int h=0;h<HH;h++) red[warp][h]=acc[h];
    }
    __syncthreads();
    if(threadIdx.x<HH){
        float s=0.f;
        #pragma unroll
        for(int w2=0;w2<8;w2++) s+=red[w2][threadIdx.x];
        logits[(size_t)row*HH+threadIdx.x]=s;
    }
}

__global__ void k_max(const float* __restrict__ logits, float* __restrict__ gmax){
    const int b = blockIdx.x >> 4, h = blockIdx.x & 15;
    float m = -3.4e38f;
    for(int s=threadIdx.x; s<SS; s+=256)
        m = fmaxf(m, logits[((size_t)(b*SS+s))*HH + h]);
    __shared__ float red[256];
    red[threadIdx.x]=m; __syncthreads();
    for(int o=128;o>0;o>>=1){
        if(threadIdx.x<o) red[threadIdx.x]=fmaxf(red[threadIdx.x],red[threadIdx.x+o]);
        __syncthreads();
    }
    if(threadIdx.x==0) gmax[blockIdx.x]=red[0];
}

__global__ void k_coef(const float* __restrict__ logits, const float* __restrict__ gmax,
                       const float* __restrict__ temp, float* __restrict__ coef){
    int idx = blockIdx.x*256 + threadIdx.x;   // < 8192*16
    int h = idx & 15; int row = idx >> 4; int b = row >> 11; int s = row & 2047;
    float l = logits[idx] - gmax[b*HH+h];
    float w = expf(l * temp[h]);
    coef[idx] = w / (w * (float)(s+1) + 1e-30f);
}

// ---------------- causal cumsum (two-pass chunked) ----------------
__global__ void k_chunksum(const float* __restrict__ V, float* __restrict__ csum){
    int col   = ((blockIdx.x & 7)<<8) + threadIdx.x;
    int chunk = (blockIdx.x>>3) & 7;
    int b     = blockIdx.x>>6;
    const float* p = V + ((size_t)(b*SS + (chunk<<8)))*DD + col;
    float s=0.f;
    #pragma unroll 8
    for(int i=0;i<256;i++) s += p[(size_t)i*DD];
    csum[((size_t)(b*8+chunk))*DD + col] = s;
}

__global__ void k_scan(float* __restrict__ V, const float* __restrict__ csum,
                       const float* __restrict__ coef){
    int col   = ((blockIdx.x & 7)<<8) + threadIdx.x;
    int chunk = (blockIdx.x>>3) & 7;
    int b     = blockIdx.x>>6;
    float run = 0.f;
    for(int c=0;c<chunk;c++) run += csum[((size_t)(b*8+c))*DD + col];
    int h = col >> 7;
    float* p = V + ((size_t)(b*SS + (chunk<<8)))*DD + col;
    const float* cf = coef + ((size_t)(b*SS + (chunk<<8)))*HH + h;
    #pragma unroll 4
    for(int i=0;i<256;i++){
        run += p[(size_t)i*DD];
        p[(size_t)i*DD] = cf[i*HH] * run;
    }
}

// ---------------- row LayerNorm ----------------
__global__ void k_ln(const float* __restrict__ res, const float* __restrict__ gamma,
                     const float* __restrict__ beta, float* __restrict__ out){
    const int row = blockIdx.x;
    const float* r = res + (size_t)row*DD;
    __shared__ float srow[DD];
    __shared__ float red[8];
    int lane = threadIdx.x & 31, warp = threadIdx.x >> 5;

    float s=0.f;
    for(int d=threadIdx.x; d<DD; d+=256){ float v=r[d]; srow[d]=v; s+=v; }
    #pragma unroll
    for(int o=16;o>0;o>>=1) s += __shfl_xor_sync(0xffffffffu, s, o);
    if(lane==0) red[warp]=s;
    __syncthreads();
    float mean = (red[0]+red[1]+red[2]+red[3]+red[4]+red[5]+red[6]+red[7]) * (1.f/DD);

    float v2=0.f;
    for(int d=threadIdx.x; d<DD; d+=256){ float c=srow[d]-mean; v2+=c*c; }
    #pragma unroll
    for(int o=16;o>0;o>>=1) v2 += __shfl_xor_sync(0xffffffffu, v2, o);
    __syncthreads();
    if(lane==0) red[warp]=v2;
    __syncthreads();
    float var  = (red[0]+red[1]+red[2]+red[3]+red[4]+red[5]+red[6]+red[7]) * (1.f/DD);
    float rstd = rsqrtf(var + 1e-6f);

    for(int d=threadIdx.x; d<DD; d+=256)
        out[(size_t)row*DD + d] = (srow[d]-mean)*rstd*gamma[d] + beta[d];
}

// ---------------- launch ----------------
extern "C" void kernel_launch(void* const* d_in, const int* in_sizes, int n_in,
                              void* d_out, int out_size)
{
    const float* x      = (const float*)d_in[0];
    const float* vector = (const float*)d_in[1];
    const float* W_att  = (const float*)d_in[2];
    const float* temp   = (const float*)d_in[3];
    const float* W_val  = (const float*)d_in[4];
    const float* W_op   = (const float*)d_in[5];
    const float* ff1    = (const float*)d_in[6];
    const float* ff1_b  = (const float*)d_in[7];
    const float* ff2    = (const float*)d_in[8];
    const float* ff2_b  = (const float*)d_in[9];
    const float* gamma  = (const float*)d_in[10];
    const float* beta   = (const float*)d_in[11];
    float* out = (float*)d_out;
    (void)in_sizes; (void)n_in; (void)out_size;

    float *S1,*S2,*S3,*logits,*coef,*gmax,*csum;
    cudaGetSymbolAddress((void**)&S1, g_S1);
    cudaGetSymbolAddress((void**)&S2, g_S2);
    cudaGetSymbolAddress((void**)&S3, g_S3);
    cudaGetSymbolAddress((void**)&logits, g_logits);
    cudaGetSymbolAddress((void**)&coef, g_coef);
    cudaGetSymbolAddress((void**)&gmax, g_gmax);
    cudaGetSymbolAddress((void**)&csum, g_csum);

    dim3 gg(DD/128, MM/128);   // (16, 64)

    // attention gate (exact fp32)
    k_logits<<<MM, 256>>>(x, W_att, logits);
    k_max<<<BB*HH, 256>>>(logits, gmax);
    k_coef<<<(MM*HH)/256, 256>>>(logits, gmax, temp, coef);

    // V = x @ W_values
    k_gemm<false,false,false,false,false><<<gg,256>>>(x, nullptr, W_val, S1,
                                                      nullptr, nullptr, nullptr, DD);
    // pooled = coef * cumsum(V) (in place)
    k_chunksum<<<256,256>>>(S1, csum);
    k_scan<<<256,256>>>(S1, csum, coef);

    // op = pooled @ W_op + vector
    k_gemm<false,false,true,false,false><<<gg,256>>>(S1, nullptr, W_op, S2,
                                                     nullptr, vector, nullptr, DD);
    // h = relu([x | op] @ ff1 + ff1_b)
    k_gemm<true,true,false,true,false><<<gg,256>>>(x, S2, ff1, S3,
                                                   ff1_b, nullptr, nullptr, 2*DD);
    // res = relu(h @ ff2 + ff2_b) + x
    k_gemm<false,true,false,true,true><<<gg,256>>>(S3, nullptr, ff2, S1,
                                                   ff2_b, nullptr, x, DD);
    // out = layernorm(res) * gamma + beta
    k_ln<<<MM, 256>>>(S1, gamma, beta, out);
}

// round 2
// speedup vs baseline: 1.3139x; 1.3139x over previous
#include <cuda_runtime.h>
#include <cstdint>
#include <math.h>

#define BB 4
#define SS 2048
#define DD 2048
#define HH 16
#define MM (BB*SS)   /* 8192 */

// ---------------- scratch (allocation-free: __device__ globals) ----------------
__device__ float g_S1[(size_t)MM*DD];   // V -> pooled -> res
__device__ float g_S2[(size_t)MM*DD];   // op
__device__ float g_S3[(size_t)MM*DD];   // hidden after ff1
__device__ float g_logits[MM*HH];
__device__ float g_coef[MM*HH];
__device__ float g_gmax[BB*HH];
__device__ float g_csum[BB*8*DD];

// ---------------- helpers ----------------
__device__ __forceinline__ void mma8(float (&c)[4], const uint32_t (&a)[4], const uint32_t (&b)[2]){
    asm volatile("mma.sync.aligned.m16n8k8.row.col.f32.tf32.tf32.f32 "
        "{%0,%1,%2,%3}, {%4,%5,%6,%7}, {%8,%9}, {%0,%1,%2,%3};\n"
        : "+f"(c[0]), "+f"(c[1]), "+f"(c[2]), "+f"(c[3])
        : "r"(a[0]), "r"(a[1]), "r"(a[2]), "r"(a[3]), "r"(b[0]), "r"(b[1]));
}

__device__ __forceinline__ void cp16(void* smem_ptr, const void* gptr){
    uint32_t s = (uint32_t)__cvta_generic_to_shared(smem_ptr);
    asm volatile("cp.async.cg.shared.global [%0], [%1], 16;\n" :: "r"(s), "l"(gptr));
}
__device__ __forceinline__ void cp_commit(){ asm volatile("cp.async.commit_group;\n"); }
__device__ __forceinline__ void cp_wait1(){ asm volatile("cp.async.wait_group 1;\n"); }

// RNA-to-tf32 via integer bit trick: fp32 is sign-magnitude, so bits+0x1000 then
// HW mantissa truncation == cvt.rna.tf32 (round nearest, ties away).
#define TF32_RND 0x1000u

// ---------------- TF32 tiled GEMM, 3-stage cp.async pipeline ----------------
// C[M, 2048] = A[M, Ktot] * Bw[Ktot, 2048]   (row-major, row stride 2048)
// SPLITK: A covers k in [0,2048), A2 covers k in [2048,4096)  (logical concat)
#define STAGES 3
#define STAGE_FLOATS 8192   /* As 128x32 + Bs 32x128 */

template<bool SPLITK,bool ADDBIAS,bool ADDVEC,bool RELU,bool ADDRESID>
__global__ __launch_bounds__(256,2)
void k_gemm(const float* __restrict__ A, const float* __restrict__ A2,
            const float* __restrict__ Bw, float* __restrict__ C,
            const float* __restrict__ bias, const float* __restrict__ vec,
            const float* __restrict__ resid, int Ktot)
{
    extern __shared__ __align__(16) float sm[];   // STAGES * 32KB

    const int tid  = threadIdx.x;
    const int bM   = blockIdx.y << 7;
    const int bN   = blockIdx.x << 7;
    const int lane = tid & 31, warp = tid >> 5;
    const int wm   = (warp & 3) << 5;   // 4 warps along M
    const int wn   = (warp >> 2) << 6;  // 2 warps along N
    const int gid  = lane >> 2, tig = lane & 3;

    // precomputed per-thread load indices
    const int rA[4]  = { (tid+0)>>3, (tid+256)>>3, (tid+512)>>3, (tid+768)>>3 };
    const int cA[4]  = { tid&7, tid&7, tid&7, tid&7 };
    const int rB[4]  = { (tid+0)>>5, (tid+256)>>5, (tid+512)>>5, (tid+768)>>5 };
    const int cB     = tid & 31;

    float acc[2][8][4];
    #pragma unroll
    for(int i=0;i<2;i++)
        #pragma unroll
        for(int j=0;j<8;j++)
            #pragma unroll
            for(int k=0;k<4;k++) acc[i][j][k]=0.f;

    const int ntiles = Ktot >> 5;

    auto load_stage = [&](int kt, int slot){
        const int kbase = kt << 5;
        const float* srcA = A; int koff = kbase;
        if (SPLITK && kbase >= DD){ srcA = A2; koff = kbase - DD; }
        float* As = sm + slot*STAGE_FLOATS;
        float* Bs = As + 4096;
        #pragma unroll
        for(int i=0;i<4;i++){
            int r = rA[i], c4 = cA[i];
            cp16(&As[(r*8 + (c4 ^ (r&7)))<<2],
                 srcA + (size_t)(bM+r)*DD + koff + (c4<<2));
            int rb = rB[i];
            cp16(&Bs[(rb*32 + (cB ^ ((rb&3)<<1)))<<2],
                 Bw + (size_t)(kbase+rb)*DD + bN + (cB<<2));
        }
    };

    // prologue: stages 0,1
    load_stage(0, 0); cp_commit();
    load_stage(1, 1); cp_commit();

    for(int kt=0; kt<ntiles; kt++){
        cp_wait1();
        __syncthreads();

        const uint32_t* As = (const uint32_t*)(sm + (kt%STAGES)*STAGE_FLOATS);
        const uint32_t* Bs = As + 4096;

        #pragma unroll
        for(int kk=0; kk<32; kk+=8){
            uint32_t afr[2][4];
            const int c0 = kk>>2, c1 = (kk>>2)+1;
            #pragma unroll
            for(int mt=0;mt<2;mt++){
                int r0 = wm + (mt<<4) + gid;
                int r1 = r0 + 8;
                afr[mt][0] = As[ (r0<<5) + ((c0 ^ (r0&7))<<2) + tig ] + TF32_RND;
                afr[mt][1] = As[ (r1<<5) + ((c0 ^ (r1&7))<<2) + tig ] + TF32_RND;
                afr[mt][2] = As[ (r0<<5) + ((c1 ^ (r0&7))<<2) + tig ] + TF32_RND;
                afr[mt][3] = As[ (r1<<5) + ((c1 ^ (r1&7))<<2) + tig ] + TF32_RND;
            }
            uint32_t bfr[8][2];
            const int rB0 = kk + tig, rB1 = kk + tig + 4;
            const int sw  = (tig<<1);
            #pragma unroll
            for(int nt=0;nt<8;nt++){
                int cc = wn + (nt<<3) + gid;
                int cg = cc>>2, ce = cc&3;
                bfr[nt][0] = Bs[ (rB0<<7) + ((cg ^ sw)<<2) + ce ] + TF32_RND;
                bfr[nt][1] = Bs[ (rB1<<7) + ((cg ^ sw)<<2) + ce ] + TF32_RND;
            }
            #pragma unroll
            for(int mt=0;mt<2;mt++)
                #pragma unroll
                for(int nt=0;nt<8;nt++)
                    mma8(acc[mt][nt], afr[mt], bfr[nt]);
        }

        int nk = kt + STAGES - 1;
        if (nk < ntiles) load_stage(nk, nk%STAGES);
        cp_commit();
    }

    // epilogue
    #pragma unroll
    for(int mt=0;mt<2;mt++){
        #pragma unroll
        for(int nt=0;nt<8;nt++){
            int col = bN + wn + (nt<<3) + (tig<<1);
            #pragma unroll
            for(int rr=0;rr<2;rr++){
                int row = bM + wm + (mt<<4) + gid + (rr<<3);
                float v0 = acc[mt][nt][rr*2+0];
                float v1 = acc[mt][nt][rr*2+1];
                if (ADDBIAS){ v0 += bias[col]; v1 += bias[col+1]; }
                if (ADDVEC){ int b0 = row>>11; v0 += vec[b0*DD+col]; v1 += vec[b0*DD+col+1]; }
                if (RELU){ v0 = fmaxf(v0,0.f); v1 = fmaxf(v1,0.f); }
                if (ADDRESID){
                    v0 += resid[(size_t)row*DD+col];
                    v1 += resid[(size_t)row*DD+col+1];
                }
                *(float2*)(C + (size_t)row*DD + col) = make_float2(v0,v1);
            }
        }
    }
}

// ---------------- attention gate: logits = x @ W_att (fp32 exact) ----------------
// W_att cached (transposed) in 128KB dynamic smem once per block; 32 rows/block.
__global__ __launch_bounds__(256)
void k_logits2(const float* __restrict__ x, const float* __restrict__ Watt,
               float* __restrict__ logits)
{
    extern __shared__ float sW[];           // [16][2048] transposed
    __shared__ float red[8][HH];
    for(int i=threadIdx.x; i<DD*HH; i+=256){
        int d=i>>4, h=i&15;
        sW[h*DD + d] = Watt[i];
    }
    __syncthreads();

    const int warp = threadIdx.x>>5, lanei = threadIdx.x&31;
    const int rbase = blockIdx.x << 5;
    for(int rl=0; rl<32; rl++){
        const int row = rbase + rl;
        const float* xr = x + (size_t)row*DD;
        float acc[HH];
        #pragma unroll
        for(int h=0;h<HH;h++) acc[h]=0.f;
        for(int d=threadIdx.x; d<DD; d+=256){
            float xv = xr[d];
            #pragma unroll
            for(int h=0;h<HH;h++) acc[h] += xv * sW[h*DD + d];
        }
        #pragma unroll
        for(int h=0;h<HH;h++){
            #pragma unroll
            for(int o=16;o>0;o>>=1) acc[h] += __shfl_xor_sync(0xffffffffu, acc[h], o);
        }
        if(lanei==0){
            #pragma unroll
            for(int h=0;h<HH;h++) red[warp][h]=acc[h];
        }
        __syncthreads();
        if(threadIdx.x<HH){
            float s=0.f;
            #pragma unroll
            for(int w2=0;w2<8;w2++) s+=red[w2][threadIdx.x];
            logits[(size_t)row*HH+threadIdx.x]=s;
        }
        __syncthreads();
    }
}

__global__ void k_max(const float* __restrict__ logits, float* __restrict__ gmax){
    const int b = blockIdx.x >> 4, h = blockIdx.x & 15;
    float m = -3.4e38f;
    for(int s=threadIdx.x; s<SS; s+=256)
        m = fmaxf(m, logits[((size_t)(b*SS+s))*HH + h]);
    __shared__ float red[256];
    red[threadIdx.x]=m; __syncthreads();
    for(int o=128;o>0;o>>=1){
        if(threadIdx.x<o) red[threadIdx.x]=fmaxf(red[threadIdx.x],red[threadIdx.x+o]);
        __syncthreads();
    }
    if(threadIdx.x==0) gmax[blockIdx.x]=red[0];
}

__global__ void k_coef(const float* __restrict__ logits, const float* __restrict__ gmax,
                       const float* __restrict__ temp, float* __restrict__ coef){
    int idx = blockIdx.x*256 + threadIdx.x;   // < 8192*16
    int h = idx & 15; int row = idx >> 4; int b = row >> 11; int s = row & 2047;
    float l = logits[idx] - gmax[b*HH+h];
    float w = expf(l * temp[h]);
    coef[idx] = w / (w * (float)(s+1) + 1e-30f);
}

// ---------------- causal cumsum (two-pass chunked) ----------------
__global__ void k_chunksum(const float* __restrict__ V, float* __restrict__ csum){
    int col   = ((blockIdx.x & 7)<<8) + threadIdx.x;
    int chunk = (blockIdx.x>>3) & 7;
    int b     = blockIdx.x>>6;
    const float* p = V + ((size_t)(b*SS + (chunk<<8)))*DD + col;
    float s=0.f;
    #pragma unroll 8
    for(int i=0;i<256;i++) s += p[(size_t)i*DD];
    csum[((size_t)(b*8+chunk))*DD + col] = s;
}

__global__ void k_scan(float* __restrict__ V, const float* __restrict__ csum,
                       const float* __restrict__ coef){
    int col   = ((blockIdx.x & 7)<<8) + threadIdx.x;
    int chunk = (blockIdx.x>>3) & 7;
    int b     = blockIdx.x>>6;
    float run = 0.f;
    for(int c=0;c<chunk;c++) run += csum[((size_t)(b*8+c))*DD + col];
    int h = col >> 7;
    float* p = V + ((size_t)(b*SS + (chunk<<8)))*DD + col;
    const float* cf = coef + ((size_t)(b*SS + (chunk<<8)))*HH + h;
    #pragma unroll 4
    for(int i=0;i<256;i++){
        run += p[(size_t)i*DD];
        p[(size_t)i*DD] = cf[i*HH] * run;
    }
}

// ---------------- row LayerNorm ----------------
__global__ void k_ln(const float* __restrict__ res, const float* __restrict__ gamma,
                     const float* __restrict__ beta, float* __restrict__ out){
    const int row = blockIdx.x;
    const float* r = res + (size_t)row*DD;
    __shared__ float srow[DD];
    __shared__ float red[8];
    int lane = threadIdx.x & 31, warp = threadIdx.x >> 5;

    float s=0.f;
    for(int d=threadIdx.x; d<DD; d+=256){ float v=r[d]; srow[d]=v; s+=v; }
    #pragma unroll
    for(int o=16;o>0;o>>=1) s += __shfl_xor_sync(0xffffffffu, s, o);
    if(lane==0) red[warp]=s;
    __syncthreads();
    float mean = (red[0]+red[1]+red[2]+red[3]+red[4]+red[5]+red[6]+red[7]) * (1.f/DD);

    float v2=0.f;
    for(int d=threadIdx.x; d<DD; d+=256){ float c=srow[d]-mean; v2+=c*c; }
    #pragma unroll
    for(int o=16;o>0;o>>=1) v2 += __shfl_xor_sync(0xffffffffu, v2, o);
    __syncthreads();
    if(lane==0) red[warp]=v2;
    __syncthreads();
    float var  = (red[0]+red[1]+red[2]+red[3]+red[4]+red[5]+red[6]+red[7]) * (1.f/DD);
    float rstd = rsqrtf(var + 1e-6f);

    for(int d=threadIdx.x; d<DD; d+=256)
        out[(size_t)row*DD + d] = (srow[d]-mean)*rstd*gamma[d] + beta[d];
}

// ---------------- launch ----------------
extern "C" void kernel_launch(void* const* d_in, const int* in_sizes, int n_in,
                              void* d_out, int out_size)
{
    const float* x      = (const float*)d_in[0];
    const float* vector = (const float*)d_in[1];
    const float* W_att  = (const float*)d_in[2];
    const float* temp   = (const float*)d_in[3];
    const float* W_val  = (const float*)d_in[4];
    const float* W_op   = (const float*)d_in[5];
    const float* ff1    = (const float*)d_in[6];
    const float* ff1_b  = (const float*)d_in[7];
    const float* ff2    = (const float*)d_in[8];
    const float* ff2_b  = (const float*)d_in[9];
    const float* gamma  = (const float*)d_in[10];
    const float* beta   = (const float*)d_in[11];
    float* out = (float*)d_out;
    (void)in_sizes; (void)n_in; (void)out_size;

    float *S1,*S2,*S3,*logits,*coef,*gmax,*csum;
    cudaGetSymbolAddress((void**)&S1, g_S1);
    cudaGetSymbolAddress((void**)&S2, g_S2);
    cudaGetSymbolAddress((void**)&S3, g_S3);
    cudaGetSymbolAddress((void**)&logits, g_logits);
    cudaGetSymbolAddress((void**)&coef, g_coef);
    cudaGetSymbolAddress((void**)&gmax, g_gmax);
    cudaGetSymbolAddress((void**)&csum, g_csum);

    const int gemm_smem = STAGES * STAGE_FLOATS * 4;   // 96KB
    const int logit_smem = DD * HH * 4;                // 128KB
    cudaFuncSetAttribute(k_gemm<false,false,false,false,false>,
                         cudaFuncAttributeMaxDynamicSharedMemorySize, gemm_smem);
    cudaFuncSetAttribute(k_gemm<false,false,true,false,false>,
                         cudaFuncAttributeMaxDynamicSharedMemorySize, gemm_smem);
    cudaFuncSetAttribute(k_gemm<true,true,false,true,false>,
                         cudaFuncAttributeMaxDynamicSharedMemorySize, gemm_smem);
    cudaFuncSetAttribute(k_gemm<false,true,false,true,true>,
                         cudaFuncAttributeMaxDynamicSharedMemorySize, gemm_smem);
    cudaFuncSetAttribute(k_logits2,
                         cudaFuncAttributeMaxDynamicSharedMemorySize, logit_smem);

    dim3 gg(DD/128, MM/128);   // (16, 64)

    // attention gate (exact fp32)
    k_logits2<<<MM/32, 256, logit_smem>>>(x, W_att, logits);
    k_max<<<BB*HH, 256>>>(logits, gmax);
    k_coef<<<(MM*HH)/256, 256>>>(logits, gmax, temp, coef);

    // V = x @ W_values
    k_gemm<false,false,false,false,false><<<gg,256,gemm_smem>>>(x, nullptr, W_val, S1,
                                                      nullptr, nullptr, nullptr, DD);
    // pooled = coef * cumsum(V) (in place)
    k_chunksum<<<256,256>>>(S1, csum);
    k_scan<<<256,256>>>(S1, csum, coef);

    // op = pooled @ W_op + vector
    k_gemm<false,false,true,false,false><<<gg,256,gemm_smem>>>(S1, nullptr, W_op, S2,
                                                     nullptr, vector, nullptr, DD);
    // h = relu([x | op] @ ff1 + ff1_b)
    k_gemm<true,true,false,true,false><<<gg,256,gemm_smem>>>(x, S2, ff1, S3,
                                                   ff1_b, nullptr, nullptr, 2*DD);
    // res = relu(h @ ff2 + ff2_b) + x
    k_gemm<false,true,false,true,true><<<gg,256,gemm_smem>>>(S3, nullptr, ff2, S1,
                                                   ff2_b, nullptr, x, DD);
    // out = layernorm(res) * gamma + beta
    k_ln<<<MM, 256>>>(S1, gamma, beta, out);
}

// round 4
// speedup vs baseline: 1.3664x; 1.0400x over previous
#include <cuda_runtime.h>
#include <cstdint>
#include <math.h>

#define BB 4
#define SS 2048
#define DD 2048
#define HH 16
#define MM (BB*SS)   /* 8192 */

// ---------------- scratch (allocation-free: __device__ globals) ----------------
__device__ float g_S1[(size_t)MM*DD];   // V -> pooled -> res
__device__ float g_S2[(size_t)MM*DD];   // op
__device__ float g_S3[(size_t)MM*DD];   // hidden after ff1
__device__ float g_xr[(size_t)MM*DD];   // RNA-rounded x
__device__ float g_Wr[(size_t)10240*DD]; // rounded Wval | Wop | ff1 | ff2 (orig [K,N] layout)
__device__ float g_logits[MM*HH];
__device__ float g_coef[MM*HH];
__device__ float g_gmax[BB*HH];
__device__ float g_csum[BB*8*DD];

#define WVAL_O 0
#define WOP_O  ((size_t)DD*DD)
#define FF1_O  ((size_t)2*DD*DD)
#define FF2_O  ((size_t)4*DD*DD)

// exact RNA round-to-tf32 on fp32 bits (round nearest, ties away; fp32 is sign-magnitude)
__device__ __forceinline__ float rna_tf32(float f){
    uint32_t u = (__float_as_uint(f) + 0x1000u) & ~0x1FFFu;
    return __uint_as_float(u);
}

// ---------------- helpers ----------------
__device__ __forceinline__ void mma8(float (&c)[4], const uint32_t (&a)[4], const uint32_t (&b)[2]){
    asm volatile("mma.sync.aligned.m16n8k8.row.col.f32.tf32.tf32.f32 "
        "{%0,%1,%2,%3}, {%4,%5,%6,%7}, {%8,%9}, {%0,%1,%2,%3};\n"
        : "+f"(c[0]), "+f"(c[1]), "+f"(c[2]), "+f"(c[3])
        : "r"(a[0]), "r"(a[1]), "r"(a[2]), "r"(a[3]), "r"(b[0]), "r"(b[1]));
}

__device__ __forceinline__ void cp16(void* smem_ptr, const void* gptr){
    uint32_t s = (uint32_t)__cvta_generic_to_shared(smem_ptr);
    asm volatile("cp.async.cg.shared.global [%0], [%1], 16;\n" :: "r"(s), "l"(gptr));
}
__device__ __forceinline__ void cp_commit(){ asm volatile("cp.async.commit_group;\n"); }
__device__ __forceinline__ void cp_wait1(){ asm volatile("cp.async.wait_group 1;\n"); }

// ---------------- TF32 tiled GEMM, 3-stage cp.async pipeline ----------------
// C[M, 2048] = A[M, Ktot] * Bw[Ktot, 2048]   (row-major, row stride 2048)
// All operands pre-rounded to tf32 values in gmem -> no in-loop rounding.
// SPLITK: A covers k in [0,2048), A2 covers k in [2048,4096).
#define STAGES 3
#define STAGE_FLOATS 8192   /* As 128x32 + Bs 32x128 */

template<bool SPLITK,bool ADDBIAS,bool ADDVEC,bool RELU,bool ADDRESID,bool ROUND>
__global__ __launch_bounds__(256,2)
void k_gemm(const float* __restrict__ A, const float* __restrict__ A2,
            const float* __restrict__ Bw, float* __restrict__ C,
            const float* __restrict__ bias, const float* __restrict__ vec,
            const float* __restrict__ resid, int Ktot)
{
    extern __shared__ __align__(16) float sm[];   // STAGES * 32KB

    const int tid  = threadIdx.x;
    const int bM   = blockIdx.y << 7;
    const int bN   = blockIdx.x << 7;
    const int lane = tid & 31, warp = tid >> 5;
    const int wm   = (warp & 3) << 5;   // 4 warps along M
    const int wn   = (warp >> 2) << 6;  // 2 warps along N
    const int gid  = lane >> 2, tig = lane & 3;

    const int rA[4]  = { (tid+0)>>3, (tid+256)>>3, (tid+512)>>3, (tid+768)>>3 };
    const int cA     = tid & 7;
    const int rB[4]  = { (tid+0)>>5, (tid+256)>>5, (tid+512)>>5, (tid+768)>>5 };
    const int cB     = tid & 31;

    float acc[2][8][4];
    #pragma unroll
    for(int i=0;i<2;i++)
        #pragma unroll
        for(int j=0;j<8;j++)
            #pragma unroll
            for(int k=0;k<4;k++) acc[i][j][k]=0.f;

    const int ntiles = Ktot >> 5;

    auto load_stage = [&](int kt, int slot){
        const int kbase = kt << 5;
        const float* srcA = A; int koff = kbase;
        if (SPLITK && kbase >= DD){ srcA = A2; koff = kbase - DD; }
        float* As = sm + slot*STAGE_FLOATS;
        float* Bs = As + 4096;
        #pragma unroll
        for(int i=0;i<4;i++){
            int r = rA[i];
            cp16(&As[(r*8 + (cA ^ (r&7)))<<2],
                 srcA + (size_t)(bM+r)*DD + koff + (cA<<2));
            int rb = rB[i];
            cp16(&Bs[(rb*32 + (cB ^ ((rb&3)<<1)))<<2],
                 Bw + (size_t)(kbase+rb)*DD + bN + (cB<<2));
        }
    };

    load_stage(0, 0); cp_commit();
    load_stage(1, 1); cp_commit();

    for(int kt=0; kt<ntiles; kt++){
        cp_wait1();
        __syncthreads();

        const uint32_t* As = (const uint32_t*)(sm + (kt%STAGES)*STAGE_FLOATS);
        const uint32_t* Bs = As + 4096;

        #pragma unroll
        for(int kk=0; kk<32; kk+=8){
            uint32_t afr[2][4];
            const int c0 = kk>>2, c1 = (kk>>2)+1;
            #pragma unroll
            for(int mt=0;mt<2;mt++){
                int r0 = wm + (mt<<4) + gid;
                int r1 = r0 + 8;
                afr[mt][0] = As[ (r0<<5) + ((c0 ^ (r0&7))<<2) + tig ];
                afr[mt][1] = As[ (r1<<5) + ((c0 ^ (r1&7))<<2) + tig ];
                afr[mt][2] = As[ (r0<<5) + ((c1 ^ (r0&7))<<2) + tig ];
                afr[mt][3] = As[ (r1<<5) + ((c1 ^ (r1&7))<<2) + tig ];
            }
            uint32_t bfr[8][2];
            const int rB0 = kk + tig, rB1 = kk + tig + 4;
            const int sw  = (tig<<1);
            #pragma unroll
            for(int nt=0;nt<8;nt++){
                int cc = wn + (nt<<3) + gid;
                int cg = cc>>2, ce = cc&3;
                bfr[nt][0] = Bs[ (rB0<<7) + ((cg ^ sw)<<2) + ce ];
                bfr[nt][1] = Bs[ (rB1<<7) + ((cg ^ sw)<<2) + ce ];
            }
            #pragma unroll
            for(int mt=0;mt<2;mt++)
                #pragma unroll
                for(int nt=0;nt<8;nt++)
                    mma8(acc[mt][nt], afr[mt], bfr[nt]);
        }

        int nk = kt + STAGES - 1;
        if (nk < ntiles) load_stage(nk, nk%STAGES);
        cp_commit();
    }

    // epilogue
    #pragma unroll
    for(int mt=0;mt<2;mt++){
        #pragma unroll
        for(int nt=0;nt<8;nt++){
            int col = bN + wn + (nt<<3) + (tig<<1);
            #pragma unroll
            for(int rr=0;rr<2;rr++){
                int row = bM + wm + (mt<<4) + gid + (rr<<3);
                float v0 = acc[mt][nt][rr*2+0];
                float v1 = acc[mt][nt][rr*2+1];
                if (ADDBIAS){ v0 += bias[col]; v1 += bias[col+1]; }
                if (ADDVEC){ int b0 = row>>11; v0 += vec[b0*DD+col]; v1 += vec[b0*DD+col+1]; }
                if (RELU){ v0 = fmaxf(v0,0.f); v1 = fmaxf(v1,0.f); }
                if (ADDRESID){
                    v0 += resid[(size_t)row*DD+col];
                    v1 += resid[(size_t)row*DD+col+1];
                }
                if (ROUND){ v0 = rna_tf32(v0); v1 = rna_tf32(v1); }
                *(float2*)(C + (size_t)row*DD + col) = make_float2(v0,v1);
            }
        }
    }
}

// ---------------- elementwise RNA-to-tf32 round (grid-stride over float4) ----------------
__global__ void k_rnd(const float* __restrict__ src, float* __restrict__ dst, int n4){
    int i = blockIdx.x*256 + threadIdx.x;
    if (i < n4){
        float4 a = ((const float4*)src)[i];
        a.x = rna_tf32(a.x); a.y = rna_tf32(a.y);
        a.z = rna_tf32(a.z); a.w = rna_tf32(a.w);
        ((float4*)dst)[i] = a;
    }
}

// ---------------- attention gate: logits = x @ W_att (fp32 exact) ----------------
__global__ __launch_bounds__(256)
void k_logits2(const float* __restrict__ x, const float* __restrict__ Watt,
               float* __restrict__ logits)
{
    extern __shared__ float sW[];           // [16][2048] transposed
    __shared__ float red[8][HH];
    for(int i=threadIdx.x; i<DD*HH; i+=256){
        int d=i>>4, h=i&15;
        sW[h*DD + d] = Watt[i];
    }
    __syncthreads();

    const int warp = threadIdx.x>>5, lanei = threadIdx.x&31;
    const int rbase = blockIdx.x << 5;
    for(int rl=0; rl<32; rl++){
        const int row = rbase + rl;
        const float* xr = x + (size_t)row*DD;
        float acc[HH];
        #pragma unroll
        for(int h=0;h<HH;h++) acc[h]=0.f;
        for(int d=threadIdx.x; d<DD; d+=256){
            float xv = xr[d];
            #pragma unroll
            for(int h=0;h<HH;h++) acc[h] += xv * sW[h*DD + d];
        }
        #pragma unroll
        for(int h=0;h<HH;h++){
            #pragma unroll
            for(int o=16;o>0;o>>=1) acc[h] += __shfl_xor_sync(0xffffffffu, acc[h], o);
        }
        if(lanei==0){
            #pragma unroll
            for(int h=0;h<HH;h++) red[warp][h]=acc[h];
        }
        __syncthreads();
        if(threadIdx.x<HH){
            float s=0.f;
            #pragma unroll
            for(int w2=0;w2<8;w2++) s+=red[w2][threadIdx.x];
            logits[(size_t)row*HH+threadIdx.x]=s;
        }
        __syncthreads();
    }
}

__global__ void k_max(const float* __restrict__ logits, float* __restrict__ gmax){
    const int b = blockIdx.x >> 4, h = blockIdx.x & 15;
    float m = -3.4e38f;
    for(int s=threadIdx.x; s<SS; s+=256)
        m = fmaxf(m, logits[((size_t)(b*SS+s))*HH + h]);
    __shared__ float red[256];
    red[threadIdx.x]=m; __syncthreads();
    for(int o=128;o>0;o>>=1){
        if(threadIdx.x<o) red[threadIdx.x]=fmaxf(red[threadIdx.x],red[threadIdx.x+o]);
        __syncthreads();
    }
    if(threadIdx.x==0) gmax[blockIdx.x]=red[0];
}

__global__ void k_coef(const float* __restrict__ logits, const float* __restrict__ gmax,
                       const float* __restrict__ temp, float* __restrict__ coef){
    int idx = blockIdx.x*256 + threadIdx.x;
    int h = idx & 15; int row = idx >> 4; int b = row >> 11; int s = row & 2047;
    float l = logits[idx] - gmax[b*HH+h];
    float w = expf(l * temp[h]);
    coef[idx] = w / (w * (float)(s+1) + 1e-30f);
}

// ---------------- causal cumsum (two-pass chunked) ----------------
__global__ void k_chunksum(const float* __restrict__ V, float* __restrict__ csum){
    int col   = ((blockIdx.x & 7)<<8) + threadIdx.x;
    int chunk = (blockIdx.x>>3) & 7;
    int b     = blockIdx.x>>6;
    const float* p = V + ((size_t)(b*SS + (chunk<<8)))*DD + col;
    float s=0.f;
    #pragma unroll 8
    for(int i=0;i<256;i++) s += p[(size_t)i*DD];
    csum[((size_t)(b*8+chunk))*DD + col] = s;
}

// scan + coef multiply; store RNA-rounded (feeds op GEMM as A operand)
__global__ void k_scan(float* __restrict__ V, const float* __restrict__ csum,
                       const float* __restrict__ coef){
    int col   = ((blockIdx.x & 7)<<8) + threadIdx.x;
    int chunk = (blockIdx.x>>3) & 7;
    int b     = blockIdx.x>>6;
    float run = 0.f;
    for(int c=0;c<chunk;c++) run += csum[((size_t)(b*8+c))*DD + col];
    int h = col >> 7;
    float* p = V + ((size_t)(b*SS + (chunk<<8)))*DD + col;
    const float* cf = coef + ((size_t)(b*SS + (chunk<<8)))*HH + h;
    #pragma unroll 4
    for(int i=0;i<256;i++){
        run += p[(size_t)i*DD];
        p[(size_t)i*DD] = rna_tf32(cf[i*HH] * run);
    }
}

// ---------------- row LayerNorm ----------------
__global__ void k_ln(const float* __restrict__ res, const float* __restrict__ gamma,
                     const float* __restrict__ beta, float* __restrict__ out){
    const int row = blockIdx.x;
    const float* r = res + (size_t)row*DD;
    __shared__ float srow[DD];
    __shared__ float red[8];
    int lane = threadIdx.x & 31, warp = threadIdx.x >> 5;

    float s=0.f;
    for(int d=threadIdx.x; d<DD; d+=256){ float v=r[d]; srow[d]=v; s+=v; }
    #pragma unroll
    for(int o=16;o>0;o>>=1) s += __shfl_xor_sync(0xffffffffu, s, o);
    if(lane==0) red[warp]=s;
    __syncthreads();
    float mean = (red[0]+red[1]+red[2]+red[3]+red[4]+red[5]+red[6]+red[7]) * (1.f/DD);

    float v2=0.f;
    for(int d=threadIdx.x; d<DD; d+=256){ float c=srow[d]-mean; v2+=c*c; }
    #pragma unroll
    for(int o=16;o>0;o>>=1) v2 += __shfl_xor_sync(0xffffffffu, v2, o);
    __syncthreads();
    if(lane==0) red[warp]=v2;
    __syncthreads();
    float var  = (red[0]+red[1]+red[2]+red[3]+red[4]+red[5]+red[6]+red[7]) * (1.f/DD);
    float rstd = rsqrtf(var + 1e-6f);

    for(int d=threadIdx.x; d<DD; d+=256)
        out[(size_t)row*DD + d] = (srow[d]-mean)*rstd*gamma[d] + beta[d];
}

// ---------------- launch ----------------
extern "C" void kernel_launch(void* const* d_in, const int* in_sizes, int n_in,
                              void* d_out, int out_size)
{
    const float* x      = (const float*)d_in[0];
    const float* vector = (const float*)d_in[1];
    const float* W_att  = (const float*)d_in[2];
    const float* temp   = (const float*)d_in[3];
    const float* W_val  = (const float*)d_in[4];
    const float* W_op   = (const float*)d_in[5];
    const float* ff1    = (const float*)d_in[6];
    const float* ff1_b  = (const float*)d_in[7];
    const float* ff2    = (const float*)d_in[8];
    const float* ff2_b  = (const float*)d_in[9];
    const float* gamma  = (const float*)d_in[10];
    const float* beta   = (const float*)d_in[11];
    float* out = (float*)d_out;
    (void)in_sizes; (void)n_in; (void)out_size;

    float *S1,*S2,*S3,*xr,*Wr,*logits,*coef,*gmax,*csum;
    cudaGetSymbolAddress((void**)&S1, g_S1);
    cudaGetSymbolAddress((void**)&S2, g_S2);
    cudaGetSymbolAddress((void**)&S3, g_S3);
    cudaGetSymbolAddress((void**)&xr, g_xr);
    cudaGetSymbolAddress((void**)&Wr, g_Wr);
    cudaGetSymbolAddress((void**)&logits, g_logits);
    cudaGetSymbolAddress((void**)&coef, g_coef);
    cudaGetSymbolAddress((void**)&gmax, g_gmax);
    cudaGetSymbolAddress((void**)&csum, g_csum);

    const int gemm_smem = STAGES * STAGE_FLOATS * 4;   // 96KB
    const int logit_smem = DD * HH * 4;                // 128KB
    cudaFuncSetAttribute(k_gemm<false,false,false,false,false,false>,
                         cudaFuncAttributeMaxDynamicSharedMemorySize, gemm_smem);
    cudaFuncSetAttribute(k_gemm<false,false,true,false,false,true>,
                         cudaFuncAttributeMaxDynamicSharedMemorySize, gemm_smem);
    cudaFuncSetAttribute(k_gemm<true,true,false,true,false,true>,
                         cudaFuncAttributeMaxDynamicSharedMemorySize, gemm_smem);
    cudaFuncSetAttribute(k_gemm<false,true,false,true,true,false>,
                         cudaFuncAttributeMaxDynamicSharedMemorySize, gemm_smem);
    cudaFuncSetAttribute(k_logits2,
                         cudaFuncAttributeMaxDynamicSharedMemorySize, logit_smem);

    // pre-round weights and x to exact tf32 values (one-time elementwise passes)
    k_rnd<<<(DD*DD/4+255)/256, 256>>>(W_val, Wr + WVAL_O, DD*DD/4);
    k_rnd<<<(DD*DD/4+255)/256, 256>>>(W_op,  Wr + WOP_O,  DD*DD/4);
    k_rnd<<<(2*DD*DD/4+255)/256, 256>>>(ff1, Wr + FF1_O,  2*DD*DD/4);
    k_rnd<<<(DD*DD/4+255)/256, 256>>>(ff2,  Wr + FF2_O,   DD*DD/4);
    k_rnd<<<(MM*DD/4+255)/256, 256>>>(x, xr, MM*DD/4);

    // attention gate (exact fp32)
    k_logits2<<<MM/32, 256, logit_smem>>>(x, W_att, logits);
    k_max<<<BB*HH, 256>>>(logits, gmax);
    k_coef<<<(MM*HH)/256, 256>>>(logits, gmax, temp, coef);

    dim3 gg(DD/128, MM/128);   // (16, 64)

    // V = x @ W_values (store fp32; scan rounds on store)
    k_gemm<false,false,false,false,false,false><<<gg,256,gemm_smem>>>(
        xr, nullptr, Wr + WVAL_O, S1, nullptr, nullptr, nullptr, DD);
    // pooled = coef * cumsum(V) (in place, rounded on store)
    k_chunksum<<<256,256>>>(S1, csum);
    k_scan<<<256,256>>>(S1, csum, coef);
    // op = pooled @ W_op + vector  (rounded store: feeds ff1 as A2)
    k_gemm<false,false,true,false,false,true><<<gg,256,gemm_smem>>>(
        S1, nullptr, Wr + WOP_O, S2, nullptr, vector, nullptr, DD);
    // h = relu([x | op] @ ff1 + b)  (rounded store: feeds ff2)
    k_gemm<true,true,false,true,false,true><<<gg,256,gemm_smem>>>(
        xr, S2, Wr + FF1_O, S3, ff1_b, nullptr, nullptr, 2*DD);
    // res = relu(h @ ff2 + b) + x   (exact store)
    k_gemm<false,true,false,true,true,false><<<gg,256,gemm_smem>>>(
        S3, nullptr, Wr + FF2_O, S1, ff2_b, nullptr, x, DD);
    // out = layernorm(res)
    k_ln<<<MM, 256>>>(S1, gamma, beta, out);
}

// round 5
// speedup vs baseline: 1.3990x; 1.0238x over previous
#include <cuda_runtime.h>
#include <cstdint>
#include <math.h>

#define BB 4
#define SS 2048
#define DD 2048
#define HH 16
#define MM (BB*SS)   /* 8192 */

// ---------------- scratch (allocation-free: __device__ globals) ----------------
__device__ float g_S1[(size_t)MM*DD];   // V -> pooled -> res
__device__ float g_S2[(size_t)MM*DD];   // op
__device__ float g_S3[(size_t)MM*DD];   // hidden after ff1
__device__ float g_xr[(size_t)MM*DD];   // RNA-rounded x
__device__ float g_Wt[(size_t)10240*DD]; // rounded+transposed [N][K]: Wval|Wop|ff1|ff2
__device__ float g_logits[MM*HH];
__device__ float g_coef[MM*HH];
__device__ float g_gmax[BB*HH];
__device__ float g_csum[BB*8*DD];

#define WVAL_T 0
#define WOP_T  ((size_t)DD*DD)
#define FF1_T  ((size_t)2*DD*DD)
#define FF2_T  ((size_t)4*DD*DD)

// exact RNA round-to-tf32 on fp32 bits (round nearest, ties away; fp32 is sign-magnitude)
__device__ __forceinline__ float rna_tf32(float f){
    uint32_t u = (__float_as_uint(f) + 0x1000u) & ~0x1FFFu;
    return __uint_as_float(u);
}

// ---------------- helpers ----------------
__device__ __forceinline__ void mma8(float (&c)[4], const uint32_t (&a)[4],
                                     uint32_t b0, uint32_t b1){
    asm volatile("mma.sync.aligned.m16n8k8.row.col.f32.tf32.tf32.f32 "
        "{%0,%1,%2,%3}, {%4,%5,%6,%7}, {%8,%9}, {%0,%1,%2,%3};\n"
        : "+f"(c[0]), "+f"(c[1]), "+f"(c[2]), "+f"(c[3])
        : "r"(a[0]), "r"(a[1]), "r"(a[2]), "r"(a[3]), "r"(b0), "r"(b1));
}

__device__ __forceinline__ void ldsm4(uint32_t (&d)[4], uint32_t saddr){
    asm volatile("ldmatrix.sync.aligned.m8n8.x4.shared.b16 {%0,%1,%2,%3}, [%4];"
        : "=r"(d[0]), "=r"(d[1]), "=r"(d[2]), "=r"(d[3]) : "r"(saddr));
}

__device__ __forceinline__ void cp16(uint32_t saddr, const void* gptr){
    asm volatile("cp.async.cg.shared.global [%0], [%1], 16;\n" :: "r"(saddr), "l"(gptr));
}
__device__ __forceinline__ void cp_commit(){ asm volatile("cp.async.commit_group;\n"); }
__device__ __forceinline__ void cp_wait1(){ asm volatile("cp.async.wait_group 1;\n"); }

// ---------------- TF32 tiled GEMM, 3-stage cp.async + ldmatrix ----------------
// C[M, 2048] = A[M, Ktot] * Bt^T where Bt is [2048(N), Ktot] K-major
// (weights pre-transposed + pre-rounded). A is [M][K] row-major, pre-rounded.
// SPLITK: A covers k in [0,2048), A2 covers k in [2048,4096).
#define STAGES 3
#define STAGE_BYTES 32768   /* As 128x32 f32 (16KB) + Bs 128x32 f32 (16KB) */

template<bool SPLITK,bool ADDBIAS,bool ADDVEC,bool RELU,bool ADDRESID,bool ROUND>
__global__ __launch_bounds__(256,2)
void k_gemm(const float* __restrict__ A, const float* __restrict__ A2,
            const float* __restrict__ Bt, float* __restrict__ C,
            const float* __restrict__ bias, const float* __restrict__ vec,
            const float* __restrict__ resid, int Ktot)
{
    extern __shared__ __align__(16) float sm[];   // STAGES * 32KB
    const uint32_t smb = (uint32_t)__cvta_generic_to_shared(sm);

    const int tid  = threadIdx.x;
    const int bM   = blockIdx.y << 7;
    const int bN   = blockIdx.x << 7;
    const int lane = tid & 31, warp = tid >> 5;
    const int wm   = (warp & 3) << 5;   // 4 warps along M
    const int wn   = (warp >> 2) << 6;  // 2 warps along N
    const int gid  = lane >> 2, tig = lane & 3;   // epilogue mapping

    // ldmatrix per-thread row geometry (swizzle XOR mask degenerates to lr)
    const int lr = lane & 7;
    const int qh = (lane >> 3) & 1;     // row-half within x4
    const int cs = lane >> 4;           // k-group select within x4
    uint32_t aOff[2], bOff[4];
    #pragma unroll
    for(int mt=0; mt<2; mt++) aOff[mt] = (uint32_t)((wm + mt*16 + qh*8 + lr) * 128);
    #pragma unroll
    for(int p=0; p<4; p++)    bOff[p]  = (uint32_t)((wn + (2*p+qh)*8 + lr) * 128);

    // cp.async indices (both tiles: 128 rows x 8 float4-groups)
    const int rL[4] = { (tid+0)>>3, (tid+256)>>3, (tid+512)>>3, (tid+768)>>3 };
    const int cL    = tid & 7;

    float acc[2][8][4];
    #pragma unroll
    for(int i=0;i<2;i++)
        #pragma unroll
        for(int j=0;j<8;j++)
            #pragma unroll
            for(int k=0;k<4;k++) acc[i][j][k]=0.f;

    const int ntiles = Ktot >> 5;

    auto load_stage = [&](int kt, int slot){
        const int kbase = kt << 5;
        const float* srcA = A; int koff = kbase;
        if (SPLITK && kbase >= DD){ srcA = A2; koff = kbase - DD; }
        const uint32_t aBase = smb + slot*STAGE_BYTES;
        const uint32_t bBase = aBase + 16384;
        #pragma unroll
        for(int i=0;i<4;i++){
            int r = rL[i];
            uint32_t soff = (uint32_t)((r*8 + (cL ^ (r&7)))<<4);
            cp16(aBase + soff, srcA + (size_t)(bM+r)*DD + koff + (cL<<2));
            cp16(bBase + soff, Bt + (size_t)(bN+r)*Ktot + kbase + (cL<<2));
        }
    };

    load_stage(0, 0); cp_commit();
    load_stage(1, 1); cp_commit();

    for(int kt=0; kt<ntiles; kt++){
        cp_wait1();
        __syncthreads();

        const uint32_t aBase = smb + (kt%STAGES)*STAGE_BYTES;
        const uint32_t bBase = aBase + 16384;

        #pragma unroll
        for(int kk=0; kk<32; kk+=8){
            const uint32_t xoff = (uint32_t)(((((kk>>2)+cs) ^ lr)) << 4);
            uint32_t afr[2][4];
            ldsm4(afr[0], aBase + aOff[0] + xoff);
            ldsm4(afr[1], aBase + aOff[1] + xoff);
            uint32_t bf[4][4];   // [pair][b0e,b0o,b1e,b1o]
            #pragma unroll
            for(int p=0;p<4;p++) ldsm4(bf[p], bBase + bOff[p] + xoff);

            #pragma unroll
            for(int mt=0;mt<2;mt++)
                #pragma unroll
                for(int nt=0;nt<8;nt++)
                    mma8(acc[mt][nt], afr[mt], bf[nt>>1][nt&1], bf[nt>>1][2+(nt&1)]);
        }

        int nk = kt + STAGES - 1;
        if (nk < ntiles) load_stage(nk, nk%STAGES);
        cp_commit();
    }

    // epilogue (fragment C layout: thread (gid,tig): rows gid, gid+8; cols 2*tig, 2*tig+1)
    #pragma unroll
    for(int mt=0;mt<2;mt++){
        #pragma unroll
        for(int nt=0;nt<8;nt++){
            int col = bN + wn + (nt<<3) + (tig<<1);
            #pragma unroll
            for(int rr=0;rr<2;rr++){
                int row = bM + wm + (mt<<4) + gid + (rr<<3);
                float v0 = acc[mt][nt][rr*2+0];
                float v1 = acc[mt][nt][rr*2+1];
                if (ADDBIAS){ v0 += bias[col]; v1 += bias[col+1]; }
                if (ADDVEC){ int b0 = row>>11; v0 += vec[b0*DD+col]; v1 += vec[b0*DD+col+1]; }
                if (RELU){ v0 = fmaxf(v0,0.f); v1 = fmaxf(v1,0.f); }
                if (ADDRESID){
                    v0 += resid[(size_t)row*DD+col];
                    v1 += resid[(size_t)row*DD+col+1];
                }
                if (ROUND){ v0 = rna_tf32(v0); v1 = rna_tf32(v1); }
                *(float2*)(C + (size_t)row*DD + col) = make_float2(v0,v1);
            }
        }
    }
}

// ---------------- weight transpose + RNA pre-round: Wt[n][k] = rnd(W[k][n]) ----------------
__global__ void k_tr(const float* __restrict__ W, float* __restrict__ Wt, int K, int N){
    __shared__ float t[32][33];
    const int nb = blockIdx.x*32, kb = blockIdx.y*32;
    const int tx = threadIdx.x, ty = threadIdx.y;
    #pragma unroll
    for(int i=0;i<32;i+=8) t[ty+i][tx] = W[(size_t)(kb+ty+i)*N + nb+tx];
    __syncthreads();
    #pragma unroll
    for(int i=0;i<32;i+=8)
        Wt[(size_t)(nb+ty+i)*K + kb+tx] = rna_tf32(t[tx][ty+i]);
}

// rounded copy of x
__global__ void k_rnd(const float* __restrict__ src, float* __restrict__ dst, int n4){
    int i = blockIdx.x*256 + threadIdx.x;
    if (i < n4){
        float4 a = ((const float4*)src)[i];
        a.x = rna_tf32(a.x); a.y = rna_tf32(a.y);
        a.z = rna_tf32(a.z); a.w = rna_tf32(a.w);
        ((float4*)dst)[i] = a;
    }
}

// ---------------- attention gate: logits = x @ W_att (fp32 exact) ----------------
__global__ __launch_bounds__(256)
void k_logits2(const float* __restrict__ x, const float* __restrict__ Watt,
               float* __restrict__ logits)
{
    extern __shared__ float sW[];           // [16][2048] transposed
    __shared__ float red[8][HH];
    for(int i=threadIdx.x; i<DD*HH; i+=256){
        int d=i>>4, h=i&15;
        sW[h*DD + d] = Watt[i];
    }
    __syncthreads();

    const int warp = threadIdx.x>>5, lanei = threadIdx.x&31;
    const int rbase = blockIdx.x << 5;
    for(int rl=0; rl<32; rl++){
        const int row = rbase + rl;
        const float* xr = x + (size_t)row*DD;
        float acc[HH];
        #pragma unroll
        for(int h=0;h<HH;h++) acc[h]=0.f;
        for(int d=threadIdx.x; d<DD; d+=256){
            float xv = xr[d];
            #pragma unroll
            for(int h=0;h<HH;h++) acc[h] += xv * sW[h*DD + d];
        }
        #pragma unroll
        for(int h=0;h<HH;h++){
            #pragma unroll
            for(int o=16;o>0;o>>=1) acc[h] += __shfl_xor_sync(0xffffffffu, acc[h], o);
        }
        if(lanei==0){
            #pragma unroll
            for(int h=0;h<HH;h++) red[warp][h]=acc[h];
        }
        __syncthreads();
        if(threadIdx.x<HH){
            float s=0.f;
            #pragma unroll
            for(int w2=0;w2<8;w2++) s+=red[w2][threadIdx.x];
            logits[(size_t)row*HH+threadIdx.x]=s;
        }
        __syncthreads();
    }
}

__global__ void k_max(const float* __restrict__ logits, float* __restrict__ gmax){
    const int b = blockIdx.x >> 4, h = blockIdx.x & 15;
    float m = -3.4e38f;
    for(int s=threadIdx.x; s<SS; s+=256)
        m = fmaxf(m, logits[((size_t)(b*SS+s))*HH + h]);
    __shared__ float red[256];
    red[threadIdx.x]=m; __syncthreads();
    for(int o=128;o>0;o>>=1){
        if(threadIdx.x<o) red[threadIdx.x]=fmaxf(red[threadIdx.x],red[threadIdx.x+o]);
        __syncthreads();
    }
    if(threadIdx.x==0) gmax[blockIdx.x]=red[0];
}

__global__ void k_coef(const float* __restrict__ logits, const float* __restrict__ gmax,
                       const float* __restrict__ temp, float* __restrict__ coef){
    int idx = blockIdx.x*256 + threadIdx.x;
    int h = idx & 15; int row = idx >> 4; int b = row >> 11; int s = row & 2047;
    float l = logits[idx] - gmax[b*HH+h];
    float w = expf(l * temp[h]);
    coef[idx] = w / (w * (float)(s+1) + 1e-30f);
}

// ---------------- causal cumsum (two-pass chunked) ----------------
__global__ void k_chunksum(const float* __restrict__ V, float* __restrict__ csum){
    int col   = ((blockIdx.x & 7)<<8) + threadIdx.x;
    int chunk = (blockIdx.x>>3) & 7;
    int b     = blockIdx.x>>6;
    const float* p = V + ((size_t)(b*SS + (chunk<<8)))*DD + col;
    float s=0.f;
    #pragma unroll 8
    for(int i=0;i<256;i++) s += p[(size_t)i*DD];
    csum[((size_t)(b*8+chunk))*DD + col] = s;
}

// scan + coef multiply; store RNA-rounded (feeds op GEMM as A operand)
__global__ void k_scan(float* __restrict__ V, const float* __restrict__ csum,
                       const float* __restrict__ coef){
    int col   = ((blockIdx.x & 7)<<8) + threadIdx.x;
    int chunk = (blockIdx.x>>3) & 7;
    int b     = blockIdx.x>>6;
    float run = 0.f;
    for(int c=0;c<chunk;c++) run += csum[((size_t)(b*8+c))*DD + col];
    int h = col >> 7;
    float* p = V + ((size_t)(b*SS + (chunk<<8)))*DD + col;
    const float* cf = coef + ((size_t)(b*SS + (chunk<<8)))*HH + h;
    #pragma unroll 4
    for(int i=0;i<256;i++){
        run += p[(size_t)i*DD];
        p[(size_t)i*DD] = rna_tf32(cf[i*HH] * run);
    }
}

// ---------------- row LayerNorm ----------------
__global__ void k_ln(const float* __restrict__ res, const float* __restrict__ gamma,
                     const float* __restrict__ beta, float* __restrict__ out){
    const int row = blockIdx.x;
    const float* r = res + (size_t)row*DD;
    __shared__ float srow[DD];
    __shared__ float red[8];
    int lane = threadIdx.x & 31, warp = threadIdx.x >> 5;

    float s=0.f;
    for(int d=threadIdx.x; d<DD; d+=256){ float v=r[d]; srow[d]=v; s+=v; }
    #pragma unroll
    for(int o=16;o>0;o>>=1) s += __shfl_xor_sync(0xffffffffu, s, o);
    if(lane==0) red[warp]=s;
    __syncthreads();
    float mean = (red[0]+red[1]+red[2]+red[3]+red[4]+red[5]+red[6]+red[7]) * (1.f/DD);

    float v2=0.f;
    for(int d=threadIdx.x; d<DD; d+=256){ float c=srow[d]-mean; v2+=c*c; }
    #pragma unroll
    for(int o=16;o>0;o>>=1) v2 += __shfl_xor_sync(0xffffffffu, v2, o);
    __syncthreads();
    if(lane==0) red[warp]=v2;
    __syncthreads();
    float var  = (red[0]+red[1]+red[2]+red[3]+red[4]+red[5]+red[6]+red[7]) * (1.f/DD);
    float rstd = rsqrtf(var + 1e-6f);

    for(int d=threadIdx.x; d<DD; d+=256)
        out[(size_t)row*DD + d] = (srow[d]-mean)*rstd*gamma[d] + beta[d];
}

// ---------------- launch ----------------
extern "C" void kernel_launch(void* const* d_in, const int* in_sizes, int n_in,
                              void* d_out, int out_size)
{
    const float* x      = (const float*)d_in[0];
    const float* vector = (const float*)d_in[1];
    const float* W_att  = (const float*)d_in[2];
    const float* temp   = (const float*)d_in[3];
    const float* W_val  = (const float*)d_in[4];
    const float* W_op   = (const float*)d_in[5];
    const float* ff1    = (const float*)d_in[6];
    const float* ff1_b  = (const float*)d_in[7];
    const float* ff2    = (const float*)d_in[8];
    const float* ff2_b  = (const float*)d_in[9];
    const float* gamma  = (const float*)d_in[10];
    const float* beta   = (const float*)d_in[11];
    float* out = (float*)d_out;
    (void)in_sizes; (void)n_in; (void)out_size;

    float *S1,*S2,*S3,*xr,*Wt,*logits,*coef,*gmax,*csum;
    cudaGetSymbolAddress((void**)&S1, g_S1);
    cudaGetSymbolAddress((void**)&S2, g_S2);
    cudaGetSymbolAddress((void**)&S3, g_S3);
    cudaGetSymbolAddress((void**)&xr, g_xr);
    cudaGetSymbolAddress((void**)&Wt, g_Wt);
    cudaGetSymbolAddress((void**)&logits, g_logits);
    cudaGetSymbolAddress((void**)&coef, g_coef);
    cudaGetSymbolAddress((void**)&gmax, g_gmax);
    cudaGetSymbolAddress((void**)&csum, g_csum);

    const int gemm_smem = STAGES * STAGE_BYTES;   // 96KB
    const int logit_smem = DD * HH * 4;           // 128KB
    cudaFuncSetAttribute(k_gemm<false,false,false,false,false,false>,
                         cudaFuncAttributeMaxDynamicSharedMemorySize, gemm_smem);
    cudaFuncSetAttribute(k_gemm<false,false,true,false,false,true>,
                         cudaFuncAttributeMaxDynamicSharedMemorySize, gemm_smem);
    cudaFuncSetAttribute(k_gemm<true,true,false,true,false,true>,
                         cudaFuncAttributeMaxDynamicSharedMemorySize, gemm_smem);
    cudaFuncSetAttribute(k_gemm<false,true,false,true,true,false>,
                         cudaFuncAttributeMaxDynamicSharedMemorySize, gemm_smem);
    cudaFuncSetAttribute(k_logits2,
                         cudaFuncAttributeMaxDynamicSharedMemorySize, logit_smem);

    // pre-transpose (+RNA round) weights to [N][K]; pre-round x
    dim3 trb(32,8);
    k_tr<<<dim3(DD/32, DD/32), trb>>>(W_val, Wt + WVAL_T, DD, DD);
    k_tr<<<dim3(DD/32, DD/32), trb>>>(W_op,  Wt + WOP_T,  DD, DD);
    k_tr<<<dim3(DD/32, (2*DD)/32), trb>>>(ff1, Wt + FF1_T, 2*DD, DD);
    k_tr<<<dim3(DD/32, DD/32), trb>>>(ff2,  Wt + FF2_T,  DD, DD);
    k_rnd<<<(MM*DD/4+255)/256, 256>>>(x, xr, MM*DD/4);

    // attention gate (exact fp32)
    k_logits2<<<MM/32, 256, logit_smem>>>(x, W_att, logits);
    k_max<<<BB*HH, 256>>>(logits, gmax);
    k_coef<<<(MM*HH)/256, 256>>>(logits, gmax, temp, coef);

    dim3 gg(DD/128, MM/128);   // (16, 64)

    // V = x @ W_values (store fp32; scan rounds on store)
    k_gemm<false,false,false,false,false,false><<<gg,256,gemm_smem>>>(
        xr, nullptr, Wt + WVAL_T, S1, nullptr, nullptr, nullptr, DD);
    // pooled = coef * cumsum(V) (in place, rounded on store)
    k_chunksum<<<256,256>>>(S1, csum);
    k_scan<<<256,256>>>(S1, csum, coef);
    // op = pooled @ W_op + vector  (rounded store: feeds ff1 as A2)
    k_gemm<false,false,true,false,false,true><<<gg,256,gemm_smem>>>(
        S1, nullptr, Wt + WOP_T, S2, nullptr, vector, nullptr, DD);
    // h = relu([x | op] @ ff1 + b)  (rounded store: feeds ff2)
    k_gemm<true,true,false,true,false,true><<<gg,256,gemm_smem>>>(
        xr, S2, Wt + FF1_T, S3, ff1_b, nullptr, nullptr, 2*DD);
    // res = relu(h @ ff2 + b) + x   (exact store)
    k_gemm<false,true,false,true,true,false><<<gg,256,gemm_smem>>>(
        S3, nullptr, Wt + FF2_T, S1, ff2_b, nullptr, x, DD);
    // out = layernorm(res)
    k_ln<<<MM, 256>>>(S1, gamma, beta, out);
}

// round 6
// speedup vs baseline: 2.4118x; 1.7240x over previous
#include <cuda_runtime.h>
#include <cuda_fp16.h>
#include <cstdint>
#include <math.h>

#define BB 4
#define SS 2048
#define DD 2048
#define HH 16
#define MM (BB*SS)   /* 8192 */

// ---------------- scratch (allocation-free: __device__ globals) ----------------
__device__ float  g_S1[(size_t)MM*DD];    // V (fp32) -> res (fp32)
__device__ __half g_xh[(size_t)MM*DD];    // fp16 x
__device__ __half g_ph[(size_t)MM*DD];    // fp16 pooled
__device__ __half g_oph[(size_t)MM*DD];   // fp16 op
__device__ __half g_hh[(size_t)MM*DD];    // fp16 hidden
__device__ __half g_Wth[(size_t)10240*DD];// fp16 transposed weights [N][K]: Wval|Wop|ff1|ff2
__device__ float  g_logits[MM*HH];
__device__ float  g_coef[MM*HH];
__device__ float  g_gmax[BB*HH];
__device__ float  g_csum[BB*8*DD];

#define WVAL_T 0
#define WOP_T  ((size_t)DD*DD)
#define FF1_T  ((size_t)2*DD*DD)
#define FF2_T  ((size_t)4*DD*DD)

// ---------------- helpers ----------------
__device__ __forceinline__ void mma16(float (&c)[4], const uint32_t (&a)[4],
                                      uint32_t b0, uint32_t b1){
    asm volatile("mma.sync.aligned.m16n8k16.row.col.f32.f16.f16.f32 "
        "{%0,%1,%2,%3}, {%4,%5,%6,%7}, {%8,%9}, {%0,%1,%2,%3};\n"
        : "+f"(c[0]), "+f"(c[1]), "+f"(c[2]), "+f"(c[3])
        : "r"(a[0]), "r"(a[1]), "r"(a[2]), "r"(a[3]), "r"(b0), "r"(b1));
}

__device__ __forceinline__ void ldsm4(uint32_t (&d)[4], uint32_t saddr){
    asm volatile("ldmatrix.sync.aligned.m8n8.x4.shared.b16 {%0,%1,%2,%3}, [%4];"
        : "=r"(d[0]), "=r"(d[1]), "=r"(d[2]), "=r"(d[3]) : "r"(saddr));
}

__device__ __forceinline__ void cp16(uint32_t saddr, const void* gptr){
    asm volatile("cp.async.cg.shared.global [%0], [%1], 16;\n" :: "r"(saddr), "l"(gptr));
}
__device__ __forceinline__ void cp_commit(){ asm volatile("cp.async.commit_group;\n"); }
__device__ __forceinline__ void cp_wait1(){ asm volatile("cp.async.wait_group 1;\n"); }

// ---------------- fp16 tiled GEMM: 128x128 tile, BK=64, 3-stage cp.async + ldmatrix ----
// C[M, 2048] = A[M, Ktot] * Bt^T  where A is fp16 [M][Ktot], Bt is fp16 [2048(N)][Ktot].
// SPLITK: A covers k in [0,2048), A2 covers k in [2048,4096).
#define STAGES 3
#define STAGE_BYTES 32768   /* As 128x64 fp16 (16KB) + Bs 128x64 fp16 (16KB) */

template<bool SPLITK,bool ADDBIAS,bool ADDVEC,bool RELU,bool ADDRESID,bool OUTHALF>
__global__ __launch_bounds__(256,2)
void k_gemm(const __half* __restrict__ A, const __half* __restrict__ A2,
            const __half* __restrict__ Bt, void* __restrict__ Cv,
            const float* __restrict__ bias, const float* __restrict__ vec,
            const float* __restrict__ resid, int Ktot)
{
    extern __shared__ __align__(16) char sm[];   // STAGES * 32KB
    const uint32_t smb = (uint32_t)__cvta_generic_to_shared(sm);

    const int tid  = threadIdx.x;
    const int bM   = blockIdx.y << 7;
    const int bN   = blockIdx.x << 7;
    const int lane = tid & 31, warp = tid >> 5;
    const int wm   = (warp & 3) << 5;   // 4 warps along M (32 rows each)
    const int wn   = (warp >> 2) << 6;  // 2 warps along N (64 cols each)
    const int gid  = lane >> 2, tig = lane & 3;   // epilogue mapping

    // ldmatrix per-thread geometry (XOR swizzle mask degenerates to lr since bases %16==0)
    const int lr = lane & 7;
    const int qh = (lane >> 3) & 1;     // +8 rows for lanes 8-15, 24-31
    const int cs = lane >> 4;           // +1 16B-group for lanes 16-31
    uint32_t aOff[2], bOff[4];
    #pragma unroll
    for(int mt=0; mt<2; mt++) aOff[mt] = (uint32_t)((wm + mt*16 + qh*8 + lr) * 128);
    #pragma unroll
    for(int p=0; p<4; p++)    bOff[p]  = (uint32_t)((wn + p*16 + qh*8 + lr) * 128);

    // cp.async indices: each tile = 128 rows x 8 groups of 16B
    const int rL[4] = { (tid+0)>>3, (tid+256)>>3, (tid+512)>>3, (tid+768)>>3 };
    const int cL    = tid & 7;

    float acc[2][8][4];
    #pragma unroll
    for(int i=0;i<2;i++)
        #pragma unroll
        for(int j=0;j<8;j++)
            #pragma unroll
            for(int k=0;k<4;k++) acc[i][j][k]=0.f;

    const int ntiles = Ktot >> 6;

    auto load_stage = [&](int kt, int slot){
        const int kbase = kt << 6;
        const __half* srcA = A; int koff = kbase;
        if (SPLITK && kbase >= DD){ srcA = A2; koff = kbase - DD; }
        const uint32_t aBase = smb + slot*STAGE_BYTES;
        const uint32_t bBase = aBase + 16384;
        #pragma unroll
        for(int i=0;i<4;i++){
            int r = rL[i];
            uint32_t soff = (uint32_t)((r*8 + (cL ^ (r&7)))<<4);
            cp16(aBase + soff, srcA + (size_t)(bM+r)*DD + koff + (cL<<3));
            cp16(bBase + soff, Bt + (size_t)(bN+r)*Ktot + kbase + (cL<<3));
        }
    };

    load_stage(0, 0); cp_commit();
    load_stage(1, 1); cp_commit();

    for(int kt=0; kt<ntiles; kt++){
        cp_wait1();
        __syncthreads();

        const uint32_t aBase = smb + (kt%STAGES)*STAGE_BYTES;
        const uint32_t bBase = aBase + 16384;

        #pragma unroll
        for(int ki=0; ki<4; ki++){           // 4 x k16
            const int gk = ki<<1;
            const uint32_t xoff = (uint32_t)(((gk + cs) ^ lr) << 4);
            uint32_t afr[2][4];
            ldsm4(afr[0], aBase + aOff[0] + xoff);
            ldsm4(afr[1], aBase + aOff[1] + xoff);
            uint32_t bf[4][4];   // [pair p]: {b0(nt=2p), b0(nt=2p+1), b1(nt=2p), b1(nt=2p+1)}
            #pragma unroll
            for(int p=0;p<4;p++) ldsm4(bf[p], bBase + bOff[p] + xoff);

            #pragma unroll
            for(int mt=0;mt<2;mt++)
                #pragma unroll
                for(int nt=0;nt<8;nt++)
                    mma16(acc[mt][nt], afr[mt], bf[nt>>1][nt&1], bf[nt>>1][2+(nt&1)]);
        }

        int nk = kt + STAGES - 1;
        if (nk < ntiles) load_stage(nk, nk%STAGES);
        cp_commit();
    }

    // epilogue: thread (gid,tig): rows gid, gid+8; cols 2*tig, 2*tig+1
    #pragma unroll
    for(int mt=0;mt<2;mt++){
        #pragma unroll
        for(int nt=0;nt<8;nt++){
            int col = bN + wn + (nt<<3) + (tig<<1);
            #pragma unroll
            for(int rr=0;rr<2;rr++){
                int row = bM + wm + (mt<<4) + gid + (rr<<3);
                float v0 = acc[mt][nt][rr*2+0];
                float v1 = acc[mt][nt][rr*2+1];
                if (ADDBIAS){ v0 += bias[col]; v1 += bias[col+1]; }
                if (ADDVEC){ int b0 = row>>11; v0 += vec[b0*DD+col]; v1 += vec[b0*DD+col+1]; }
                if (RELU){ v0 = fmaxf(v0,0.f); v1 = fmaxf(v1,0.f); }
                if (ADDRESID){
                    v0 += resid[(size_t)row*DD+col];
                    v1 += resid[(size_t)row*DD+col+1];
                }
                if (OUTHALF){
                    __half2 hv = __floats2half2_rn(v0, v1);
                    *(__half2*)((__half*)Cv + (size_t)row*DD + col) = hv;
                } else {
                    *(float2*)((float*)Cv + (size_t)row*DD + col) = make_float2(v0,v1);
                }
            }
        }
    }
}

// ---------------- weight transpose + fp16 convert: Wt[n][k] = h(W[k][n]) ----------------
__global__ void k_trh(const float* __restrict__ W, __half* __restrict__ Wt, int K, int N){
    __shared__ float t[32][33];
    const int nb = blockIdx.x*32, kb = blockIdx.y*32;
    const int tx = threadIdx.x, ty = threadIdx.y;
    #pragma unroll
    for(int i=0;i<32;i+=8) t[ty+i][tx] = W[(size_t)(kb+ty+i)*N + nb+tx];
    __syncthreads();
    #pragma unroll
    for(int i=0;i<32;i+=8)
        Wt[(size_t)(nb+ty+i)*K + kb+tx] = __float2half(t[tx][ty+i]);
}

// fp16 copy of x
__global__ void k_xh(const float* __restrict__ src, __half* __restrict__ dst, int n4){
    int i = blockIdx.x*256 + threadIdx.x;
    if (i < n4){
        float4 a = ((const float4*)src)[i];
        __half2 h0 = __floats2half2_rn(a.x, a.y);
        __half2 h1 = __floats2half2_rn(a.z, a.w);
        uint2 u = make_uint2(*(uint32_t*)&h0, *(uint32_t*)&h1);
        ((uint2*)dst)[i] = u;
    }
}

// ---------------- attention gate: logits = x @ W_att (fp32 exact) ----------------
__global__ __launch_bounds__(256)
void k_logits2(const float* __restrict__ x, const float* __restrict__ Watt,
               float* __restrict__ logits)
{
    extern __shared__ float sW[];           // [16][2048] transposed
    __shared__ float red[8][HH];
    for(int i=threadIdx.x; i<DD*HH; i+=256){
        int d=i>>4, h=i&15;
        sW[h*DD + d] = Watt[i];
    }
    __syncthreads();

    const int warp = threadIdx.x>>5, lanei = threadIdx.x&31;
    const int rbase = blockIdx.x << 5;
    for(int rl=0; rl<32; rl++){
        const int row = rbase + rl;
        const float* xr = x + (size_t)row*DD;
        float acc[HH];
        #pragma unroll
        for(int h=0;h<HH;h++) acc[h]=0.f;
        for(int d=threadIdx.x; d<DD; d+=256){
            float xv = xr[d];
            #pragma unroll
            for(int h=0;h<HH;h++) acc[h] += xv * sW[h*DD + d];
        }
        #pragma unroll
        for(int h=0;h<HH;h++){
            #pragma unroll
            for(int o=16;o>0;o>>=1) acc[h] += __shfl_xor_sync(0xffffffffu, acc[h], o);
        }
        if(lanei==0){
            #pragma unroll
            for(int h=0;h<HH;h++) red[warp][h]=acc[h];
        }
        __syncthreads();
        if(threadIdx.x<HH){
            float s=0.f;
            #pragma unroll
            for(int w2=0;w2<8;w2++) s+=red[w2][threadIdx.x];
            logits[(size_t)row*HH+threadIdx.x]=s;
        }
        __syncthreads();
    }
}

__global__ void k_max(const float* __restrict__ logits, float* __restrict__ gmax){
    const int b = blockIdx.x >> 4, h = blockIdx.x & 15;
    float m = -3.4e38f;
    for(int s=threadIdx.x; s<SS; s+=256)
        m = fmaxf(m, logits[((size_t)(b*SS+s))*HH + h]);
    __shared__ float red[256];
    red[threadIdx.x]=m; __syncthreads();
    for(int o=128;o>0;o>>=1){
        if(threadIdx.x<o) red[threadIdx.x]=fmaxf(red[threadIdx.x],red[threadIdx.x+o]);
        __syncthreads();
    }
    if(threadIdx.x==0) gmax[blockIdx.x]=red[0];
}

__global__ void k_coef(const float* __restrict__ logits, const float* __restrict__ gmax,
                       const float* __restrict__ temp, float* __restrict__ coef){
    int idx = blockIdx.x*256 + threadIdx.x;
    int h = idx & 15; int row = idx >> 4; int b = row >> 11; int s = row & 2047;
    float l = logits[idx] - gmax[b*HH+h];
    float w = expf(l * temp[h]);
    coef[idx] = w / (w * (float)(s+1) + 1e-30f);
}

// ---------------- causal cumsum (two-pass chunked) ----------------
__global__ void k_chunksum(const float* __restrict__ V, float* __restrict__ csum){
    int col   = ((blockIdx.x & 7)<<8) + threadIdx.x;
    int chunk = (blockIdx.x>>3) & 7;
    int b     = blockIdx.x>>6;
    const float* p = V + ((size_t)(b*SS + (chunk<<8)))*DD + col;
    float s=0.f;
    #pragma unroll 8
    for(int i=0;i<256;i++) s += p[(size_t)i*DD];
    csum[((size_t)(b*8+chunk))*DD + col] = s;
}

// scan + coef multiply; write pooled as fp16 (feeds op GEMM as A operand)
__global__ void k_scan(const float* __restrict__ V, const float* __restrict__ csum,
                       const float* __restrict__ coef, __half* __restrict__ P){
    int col   = ((blockIdx.x & 7)<<8) + threadIdx.x;
    int chunk = (blockIdx.x>>3) & 7;
    int b     = blockIdx.x>>6;
    float run = 0.f;
    for(int c=0;c<chunk;c++) run += csum[((size_t)(b*8+c))*DD + col];
    int h = col >> 7;
    const float* p = V + ((size_t)(b*SS + (chunk<<8)))*DD + col;
    __half* q = P + ((size_t)(b*SS + (chunk<<8)))*DD + col;
    const float* cf = coef + ((size_t)(b*SS + (chunk<<8)))*HH + h;
    #pragma unroll 4
    for(int i=0;i<256;i++){
        run += p[(size_t)i*DD];
        q[(size_t)i*DD] = __float2half(cf[i*HH] * run);
    }
}

// ---------------- row LayerNorm ----------------
__global__ void k_ln(const float* __restrict__ res, const float* __restrict__ gamma,
                     const float* __restrict__ beta, float* __restrict__ out){
    const int row = blockIdx.x;
    const float* r = res + (size_t)row*DD;
    __shared__ float srow[DD];
    __shared__ float red[8];
    int lane = threadIdx.x & 31, warp = threadIdx.x >> 5;

    float s=0.f;
    for(int d=threadIdx.x; d<DD; d+=256){ float v=r[d]; srow[d]=v; s+=v; }
    #pragma unroll
    for(int o=16;o>0;o>>=1) s += __shfl_xor_sync(0xffffffffu, s, o);
    if(lane==0) red[warp]=s;
    __syncthreads();
    float mean = (red[0]+red[1]+red[2]+red[3]+red[4]+red[5]+red[6]+red[7]) * (1.f/DD);

    float v2=0.f;
    for(int d=threadIdx.x; d<DD; d+=256){ float c=srow[d]-mean; v2+=c*c; }
    #pragma unroll
    for(int o=16;o>0;o>>=1) v2 += __shfl_xor_sync(0xffffffffu, v2, o);
    __syncthreads();
    if(lane==0) red[warp]=v2;
    __syncthreads();
    float var  = (red[0]+red[1]+red[2]+red[3]+red[4]+red[5]+red[6]+red[7]) * (1.f/DD);
    float rstd = rsqrtf(var + 1e-6f);

    for(int d=threadIdx.x; d<DD; d+=256)
        out[(size_t)row*DD + d] = (srow[d]-mean)*rstd*gamma[d] + beta[d];
}

// ---------------- launch ----------------
extern "C" void kernel_launch(void* const* d_in, const int* in_sizes, int n_in,
                              void* d_out, int out_size)
{
    const float* x      = (const float*)d_in[0];
    const float* vector = (const float*)d_in[1];
    const float* W_att  = (const float*)d_in[2];
    const float* temp   = (const float*)d_in[3];
    const float* W_val  = (const float*)d_in[4];
    const float* W_op   = (const float*)d_in[5];
    const float* ff1    = (const float*)d_in[6];
    const float* ff1_b  = (const float*)d_in[7];
    const float* ff2    = (const float*)d_in[8];
    const float* ff2_b  = (const float*)d_in[9];
    const float* gamma  = (const float*)d_in[10];
    const float* beta   = (const float*)d_in[11];
    float* out = (float*)d_out;
    (void)in_sizes; (void)n_in; (void)out_size;

    float *S1,*logits,*coef,*gmax,*csum;
    __half *xh,*ph,*oph,*hh,*Wth;
    cudaGetSymbolAddress((void**)&S1, g_S1);
    cudaGetSymbolAddress((void**)&xh, g_xh);
    cudaGetSymbolAddress((void**)&ph, g_ph);
    cudaGetSymbolAddress((void**)&oph, g_oph);
    cudaGetSymbolAddress((void**)&hh, g_hh);
    cudaGetSymbolAddress((void**)&Wth, g_Wth);
    cudaGetSymbolAddress((void**)&logits, g_logits);
    cudaGetSymbolAddress((void**)&coef, g_coef);
    cudaGetSymbolAddress((void**)&gmax, g_gmax);
    cudaGetSymbolAddress((void**)&csum, g_csum);

    const int gemm_smem = STAGES * STAGE_BYTES;   // 96KB
    const int logit_smem = DD * HH * 4;           // 128KB
    cudaFuncSetAttribute(k_gemm<false,false,false,false,false,false>,
                         cudaFuncAttributeMaxDynamicSharedMemorySize, gemm_smem);
    cudaFuncSetAttribute(k_gemm<false,false,true,false,false,true>,
                         cudaFuncAttributeMaxDynamicSharedMemorySize, gemm_smem);
    cudaFuncSetAttribute(k_gemm<true,true,false,true,false,true>,
                         cudaFuncAttributeMaxDynamicSharedMemorySize, gemm_smem);
    cudaFuncSetAttribute(k_gemm<false,true,false,true,true,false>,
                         cudaFuncAttributeMaxDynamicSharedMemorySize, gemm_smem);
    cudaFuncSetAttribute(k_logits2,
                         cudaFuncAttributeMaxDynamicSharedMemorySize, logit_smem);

    // weight transposes (+fp16) and fp16 x
    dim3 trb(32,8);
    k_trh<<<dim3(DD/32, DD/32), trb>>>(W_val, Wth + WVAL_T, DD, DD);
    k_trh<<<dim3(DD/32, DD/32), trb>>>(W_op,  Wth + WOP_T,  DD, DD);
    k_trh<<<dim3(DD/32, (2*DD)/32), trb>>>(ff1, Wth + FF1_T, 2*DD, DD);
    k_trh<<<dim3(DD/32, DD/32), trb>>>(ff2,  Wth + FF2_T,  DD, DD);
    k_xh<<<(MM*DD/4+255)/256, 256>>>(x, xh, MM*DD/4);

    // attention gate (exact fp32)
    k_logits2<<<MM/32, 256, logit_smem>>>(x, W_att, logits);
    k_max<<<BB*HH, 256>>>(logits, gmax);
    k_coef<<<(MM*HH)/256, 256>>>(logits, gmax, temp, coef);

    dim3 gg(DD/128, MM/128);   // (16, 64)

    // V = x @ W_values  (fp32 out)
    k_gemm<false,false,false,false,false,false><<<gg,256,gemm_smem>>>(
        xh, nullptr, Wth + WVAL_T, S1, nullptr, nullptr, nullptr, DD);
    // pooled = coef * cumsum(V)  (fp16 out)
    k_chunksum<<<256,256>>>(S1, csum);
    k_scan<<<256,256>>>(S1, csum, coef, ph);
    // op = pooled @ W_op + vector  (fp16 out)
    k_gemm<false,false,true,false,false,true><<<gg,256,gemm_smem>>>(
        ph, nullptr, Wth + WOP_T, oph, nullptr, vector, nullptr, DD);
    // h = relu([x | op] @ ff1 + b)  (fp16 out)
    k_gemm<true,true,false,true,false,true><<<gg,256,gemm_smem>>>(
        xh, oph, Wth + FF1_T, hh, ff1_b, nullptr, nullptr, 2*DD);
    // res = relu(h @ ff2 + b) + x   (fp32 out)
    k_gemm<false,true,false,true,true,false><<<gg,256,gemm_smem>>>(
        hh, nullptr, Wth + FF2_T, S1, ff2_b, nullptr, x, DD);
    // out = layernorm(res)
    k_ln<<<MM, 256>>>(S1, gamma, beta, out);
}